// round 1
// baseline (speedup 1.0000x reference)
#include <cuda_runtime.h>

// EGCL_A2V — fused fp32 implementation.
// Decomposition: e_in@We1 = node_feat@We1[0:128] (per-node, channel-indep)
//                         + vnf[b,:,c]@We1[128:256] (precomputed per (b,c))
//                         + radial * We1[256,:]
// Main kernel fuses: layer0 GEMM, silu, layer2 GEMM, silu, coord-head GEMM,
// silu, dot(Wc2), and per-graph segment accumulation (register accumulators,
// flushed via atomics only at graph boundaries — data_batch is sorted).
// Final tiny kernel does the node MLP on B*C=300 rows and writes both outputs.

#define NF 128
#define H  128
#define C  3
#define R  8              // nodes per group
#define ROWS (R*C)        // 24
#define NODES_PER_BLOCK 80
#define B_MAX 256

__device__ float g_V1[B_MAX * C * H];     // silu-input layer1 contribution per (b,c) incl. be1
__device__ float g_aggM[B_MAX * C * H];   // segment sums of m
__device__ float g_aggT[B_MAX * 9];       // segment sums of trans [b][d][c]
__device__ float g_cnt[B_MAX];            // nodes per graph

__device__ __forceinline__ float silu(float x) {
    return x / (1.0f + __expf(-x));
}

// ---------------------------------------------------------------------------
// prep: V1[b,c,h] = be1[h] + sum_f vnf[b,f,c] * We1[128+f, h]; zero accumulators
// ---------------------------------------------------------------------------
__global__ void prep_kernel(const float* __restrict__ vnf,
                            const float* __restrict__ We1,
                            const float* __restrict__ be1) {
    int h  = threadIdx.x;
    int bc = blockIdx.x;              // 0 .. B*C-1
    int b  = bc / C, c = bc % C;
    float acc = be1[h];
    const float* w = We1 + NF * H;    // rows 128..255
#pragma unroll 4
    for (int f = 0; f < NF; f++)
        acc = fmaf(vnf[(b * NF + f) * C + c], __ldg(&w[f * H + h]), acc);
    g_V1[bc * H + h]   = acc;
    g_aggM[bc * H + h] = 0.0f;
    if (bc == 0) {
        for (int i = h; i < B_MAX * 9; i += blockDim.x) g_aggT[i] = 0.0f;
        for (int i = h; i < B_MAX;     i += blockDim.x) g_cnt[i]  = 0.0f;
    }
}

// ---------------------------------------------------------------------------
// main fused kernel: thread = h (0..127), block processes NODES_PER_BLOCK nodes
// ---------------------------------------------------------------------------
__global__ void __launch_bounds__(128)
main_kernel(const float* __restrict__ node_feat,
            const float* __restrict__ coord,
            const float* __restrict__ vcoord,
            const int*   __restrict__ batch,
            const float* __restrict__ We1,
            const float* __restrict__ We2, const float* __restrict__ be2,
            const float* __restrict__ Wc1, const float* __restrict__ bc1,
            const float* __restrict__ Wc2,
            int N) {
    __shared__ __align__(16) float snf[R][NF];     // node_feat tile
    __shared__ __align__(16) float sm[ROWS][H];    // m1 then m2
    __shared__ float sdiff[R][C][3];
    __shared__ float srad[R][C];
    __shared__ int   sbid[R];
    __shared__ float ss[ROWS];                     // s per row
    __shared__ float sred[ROWS][4];

    const int h     = threadIdx.x;
    const int base0 = blockIdx.x * NODES_PER_BLOCK;

    const float wr   = __ldg(&We1[256 * H + h]);
    const float be2h = be2[h];
    const float bc1h = bc1[h];
    const float wc2h = Wc2[h];

    float aggM[C] = {0.f, 0.f, 0.f};
    float aggT    = 0.f;     // only threads 0..8 use
    float cntL    = 0.f;     // only thread 0 uses
    int   cur_b   = -1;

    for (int g = 0; g < NODES_PER_BLOCK; g += R) {
        const int base = base0 + g;

        // ---- metadata: batch ids ----
        if (h < R) {
            int n = base + h;
            sbid[h] = (n < N) ? batch[n] : -1;
        }
        __syncthreads();

        // ---- diff[r][cc][d] ----
        if (h < R * 9) {
            int r = h / 9, rem = h % 9, cc = rem / 3, d = rem % 3;
            int n = min(base + r, N - 1);
            int b = sbid[r] < 0 ? 0 : sbid[r];
            sdiff[r][cc][d] = vcoord[(b * 3 + d) * C + cc] - coord[n * 3 + d];
        }
        __syncthreads();

        // ---- radial ----
        if (h < R * C) {
            int r = h / C, cc = h % C;
            float x = sdiff[r][cc][0], y = sdiff[r][cc][1], z = sdiff[r][cc][2];
            srad[r][cc] = sqrtf(x * x + y * y + z * z);
        }

        // ---- load node_feat tile ----
#pragma unroll
        for (int r = 0; r < R; r++) {
            int n = min(base + r, N - 1);
            snf[r][h] = node_feat[(long)n * NF + h];
        }
        __syncthreads();

        // ---- layer0: x1[r] = node_feat[r] @ We1[0:128] ----
        float x1[R];
#pragma unroll
        for (int r = 0; r < R; r++) x1[r] = 0.f;
#pragma unroll 2
        for (int k = 0; k < NF; k += 2) {
            float w0 = __ldg(&We1[k * H + h]);
            float w1 = __ldg(&We1[(k + 1) * H + h]);
#pragma unroll
            for (int r = 0; r < R; r++) {
                float2 v = *(const float2*)&snf[r][k];
                x1[r] = fmaf(v.x, w0, x1[r]);
                x1[r] = fmaf(v.y, w1, x1[r]);
            }
        }

        // ---- m1 = silu(x1 + V1[b,c] + radial*wr) -> smem ----
#pragma unroll
        for (int r = 0; r < R; r++) {
            int b = sbid[r] < 0 ? 0 : sbid[r];
#pragma unroll
            for (int cc = 0; cc < C; cc++) {
                float pre = x1[r] + __ldg(&g_V1[(b * C + cc) * H + h])
                          + srad[r][cc] * wr;
                sm[r * C + cc][h] = silu(pre);
            }
        }
        __syncthreads();

        // ---- layer2: m2 = silu(m1 @ We2 + be2) ----
        float m2[ROWS];
#pragma unroll
        for (int q = 0; q < ROWS; q++) m2[q] = be2h;
#pragma unroll 2
        for (int k = 0; k < H; k += 2) {
            float w0 = __ldg(&We2[k * H + h]);
            float w1 = __ldg(&We2[(k + 1) * H + h]);
#pragma unroll
            for (int q = 0; q < ROWS; q++) {
                float2 v = *(const float2*)&sm[q][k];
                m2[q] = fmaf(v.x, w0, m2[q]);
                m2[q] = fmaf(v.y, w1, m2[q]);
            }
        }
#pragma unroll
        for (int q = 0; q < ROWS; q++) m2[q] = silu(m2[q]);
        __syncthreads();                 // all m1 reads done
#pragma unroll
        for (int q = 0; q < ROWS; q++) sm[q][h] = m2[q];
        __syncthreads();

        // ---- coord head: p = silu(m2 @ Wc1 + bc1); s = p . Wc2 ----
        float pq[ROWS];
#pragma unroll
        for (int q = 0; q < ROWS; q++) pq[q] = bc1h;
#pragma unroll 2
        for (int k = 0; k < H; k += 2) {
            float w0 = __ldg(&Wc1[k * H + h]);
            float w1 = __ldg(&Wc1[(k + 1) * H + h]);
#pragma unroll
            for (int q = 0; q < ROWS; q++) {
                float2 v = *(const float2*)&sm[q][k];
                pq[q] = fmaf(v.x, w0, pq[q]);
                pq[q] = fmaf(v.y, w1, pq[q]);
            }
        }
        {
            int lane = h & 31, wid = h >> 5;
#pragma unroll
            for (int q = 0; q < ROWS; q++) {
                float x = silu(pq[q]) * wc2h;
                x += __shfl_xor_sync(0xffffffff, x, 16);
                x += __shfl_xor_sync(0xffffffff, x, 8);
                x += __shfl_xor_sync(0xffffffff, x, 4);
                x += __shfl_xor_sync(0xffffffff, x, 2);
                x += __shfl_xor_sync(0xffffffff, x, 1);
                if (lane == 0) sred[q][wid] = x;
            }
        }
        __syncthreads();
        if (h < ROWS) ss[h] = sred[h][0] + sred[h][1] + sred[h][2] + sred[h][3];
        __syncthreads();

        // ---- segment accumulation (sorted batch -> rare flushes) ----
#pragma unroll
        for (int r = 0; r < R; r++) {
            int b = sbid[r];
            if (b < 0) continue;
            if (b != cur_b) {
                if (cur_b >= 0) {
#pragma unroll
                    for (int cc = 0; cc < C; cc++) {
                        atomicAdd(&g_aggM[(cur_b * C + cc) * H + h], aggM[cc]);
                        aggM[cc] = 0.f;
                    }
                    if (h < 9) {
                        int cc = h / 3, d = h % 3;
                        atomicAdd(&g_aggT[cur_b * 9 + d * 3 + cc], aggT);
                        aggT = 0.f;
                    }
                    if (h == 0) { atomicAdd(&g_cnt[cur_b], cntL); cntL = 0.f; }
                }
                cur_b = b;
            }
#pragma unroll
            for (int cc = 0; cc < C; cc++) aggM[cc] += m2[r * C + cc];
            if (h < 9) {
                int cc = h / 3, d = h % 3;
                aggT += sdiff[r][cc][d] * ss[r * C + cc];
            }
            if (h == 0) cntL += 1.f;
        }
        __syncthreads();   // protect sdiff/ss/sbid before next iteration
    }

    // ---- final flush ----
    if (cur_b >= 0) {
#pragma unroll
        for (int cc = 0; cc < C; cc++)
            atomicAdd(&g_aggM[(cur_b * C + cc) * H + h], aggM[cc]);
        if (h < 9) {
            int cc = h / 3, d = h % 3;
            atomicAdd(&g_aggT[cur_b * 9 + d * 3 + cc], aggT);
        }
        if (h == 0) atomicAdd(&g_cnt[cur_b], cntL);
    }
}

// ---------------------------------------------------------------------------
// finalize: node MLP on B*C rows + write both outputs
// ---------------------------------------------------------------------------
__global__ void final_kernel(const float* __restrict__ vnf,
                             const float* __restrict__ vcoord,
                             const float* __restrict__ Wn1, const float* __restrict__ bn1,
                             const float* __restrict__ Wn2, const float* __restrict__ bn2,
                             float* __restrict__ out, int B) {
    __shared__ float s_in[2 * H];
    __shared__ float s_h1[H];
    int t = threadIdx.x;
    int b = blockIdx.x / C, c = blockIdx.x % C;

    float cnt = fmaxf(g_cnt[b], 1.0f);
    s_in[t]     = vnf[(b * NF + t) * C + c];
    s_in[H + t] = g_aggM[(b * C + c) * H + t] / cnt;
    __syncthreads();

    float acc = bn1[t];
#pragma unroll 4
    for (int k = 0; k < 2 * H; k++)
        acc = fmaf(s_in[k], __ldg(&Wn1[k * H + t]), acc);
    s_h1[t] = silu(acc);
    __syncthreads();

    float acc2 = bn2[t];
#pragma unroll 4
    for (int k = 0; k < H; k++)
        acc2 = fmaf(s_h1[k], __ldg(&Wn2[k * H + t]), acc2);

    // output tensor 1: virtual_node_feat + h^T   [B, NF, C]
    out[(b * NF + t) * C + c] = vnf[(b * NF + t) * C + c] + acc2;

    // output tensor 2: virtual_coord + mean(trans)   [B, 3, C]
    if (c == 0 && t < 9) {
        int d = t / 3, cc = t % 3;
        int idx = (b * 3 + d) * C + cc;
        out[B * NF * C + idx] = vcoord[idx] + g_aggT[idx] / cnt;
    }
}

// ---------------------------------------------------------------------------
extern "C" void kernel_launch(void* const* d_in, const int* in_sizes, int n_in,
                              void* d_out, int out_size) {
    const float* node_feat = (const float*)d_in[0];
    const float* coord     = (const float*)d_in[1];
    const float* vnf       = (const float*)d_in[2];
    const float* vcoord    = (const float*)d_in[3];
    const int*   batch     = (const int*)  d_in[4];
    const float* We1 = (const float*)d_in[5];
    const float* be1 = (const float*)d_in[6];
    const float* We2 = (const float*)d_in[7];
    const float* be2 = (const float*)d_in[8];
    const float* Wc1 = (const float*)d_in[9];
    const float* bc1 = (const float*)d_in[10];
    const float* Wc2 = (const float*)d_in[11];
    const float* Wn1 = (const float*)d_in[12];
    const float* bn1 = (const float*)d_in[13];
    const float* Wn2 = (const float*)d_in[14];
    const float* bn2 = (const float*)d_in[15];

    int N = in_sizes[0] / NF;
    int B = in_sizes[2] / (NF * C);

    prep_kernel<<<B * C, 128>>>(vnf, We1, be1);

    int blocks = (N + NODES_PER_BLOCK - 1) / NODES_PER_BLOCK;
    main_kernel<<<blocks, 128>>>(node_feat, coord, vcoord, batch,
                                 We1, We2, be2, Wc1, bc1, Wc2, N);

    final_kernel<<<B * C, 128>>>(vnf, vcoord, Wn1, bn1, Wn2, bn2,
                                 (float*)d_out, B);
}

// round 2
// speedup vs baseline: 1.0497x; 1.0497x over previous
#include <cuda_runtime.h>

// EGCL_A2V — fused fp32 implementation.
// Decomposition: e_in@We1 = node_feat@We1[0:128] (per-node, channel-indep)
//                         + vnf[b,:,c]@We1[128:256] (precomputed per (b,c))
//                         + radial * We1[256,:]
// Main kernel fuses: layer0 GEMM, silu, layer2 GEMM, silu, coord-head GEMM,
// silu, dot(Wc2), and per-graph segment accumulation (register accumulators,
// flushed via atomics only at graph boundaries — data_batch is sorted).
// Final tiny kernel does the node MLP on B*C=300 rows and writes both outputs.

#define NF 128
#define H  128
#define C  3
#define R  8              // nodes per group
#define ROWS (R*C)        // 24
#define NODES_PER_BLOCK 80
#define B_MAX 256

__device__ float g_V1[B_MAX * C * H];     // silu-input layer1 contribution per (b,c) incl. be1
__device__ float g_aggM[B_MAX * C * H];   // segment sums of m
__device__ float g_aggT[B_MAX * 9];       // segment sums of trans [b][d][c]
__device__ float g_cnt[B_MAX];            // nodes per graph

__device__ __forceinline__ float silu(float x) {
    return x / (1.0f + __expf(-x));
}

// ---------------------------------------------------------------------------
// prep: V1[b,c,h] = be1[h] + sum_f vnf[b,f,c] * We1[128+f, h]; zero accumulators
// ---------------------------------------------------------------------------
__global__ void prep_kernel(const float* __restrict__ vnf,
                            const float* __restrict__ We1,
                            const float* __restrict__ be1) {
    int h  = threadIdx.x;
    int bc = blockIdx.x;              // 0 .. B*C-1
    int b  = bc / C, c = bc % C;
    float acc = be1[h];
    const float* w = We1 + NF * H;    // rows 128..255
#pragma unroll 4
    for (int f = 0; f < NF; f++)
        acc = fmaf(vnf[(b * NF + f) * C + c], __ldg(&w[f * H + h]), acc);
    g_V1[bc * H + h]   = acc;
    g_aggM[bc * H + h] = 0.0f;
    if (bc == 0) {
        for (int i = h; i < B_MAX * 9; i += blockDim.x) g_aggT[i] = 0.0f;
        for (int i = h; i < B_MAX;     i += blockDim.x) g_cnt[i]  = 0.0f;
    }
}

// ---------------------------------------------------------------------------
// main fused kernel: thread = h (0..127), block processes NODES_PER_BLOCK nodes
// ---------------------------------------------------------------------------
__global__ void __launch_bounds__(128)
main_kernel(const float* __restrict__ node_feat,
            const float* __restrict__ coord,
            const float* __restrict__ vcoord,
            const int*   __restrict__ batch,
            const float* __restrict__ We1,
            const float* __restrict__ We2, const float* __restrict__ be2,
            const float* __restrict__ Wc1, const float* __restrict__ bc1,
            const float* __restrict__ Wc2,
            int N) {
    __shared__ __align__(16) float snf[R][NF];     // node_feat tile
    __shared__ __align__(16) float sm[ROWS][H];    // m1 then m2
    __shared__ float sdiff[R][C][3];
    __shared__ float srad[R][C];
    __shared__ int   sbid[R];
    __shared__ float ss[ROWS];                     // s per row
    __shared__ float sred[ROWS][4];

    const int h     = threadIdx.x;
    const int base0 = blockIdx.x * NODES_PER_BLOCK;

    const float wr   = __ldg(&We1[256 * H + h]);
    const float be2h = be2[h];
    const float bc1h = bc1[h];
    const float wc2h = Wc2[h];

    float aggM[C] = {0.f, 0.f, 0.f};
    float aggT    = 0.f;     // only threads 0..8 use
    float cntL    = 0.f;     // only thread 0 uses
    int   cur_b   = -1;

    for (int g = 0; g < NODES_PER_BLOCK; g += R) {
        const int base = base0 + g;

        // ---- metadata: batch ids ----
        if (h < R) {
            int n = base + h;
            sbid[h] = (n < N) ? batch[n] : -1;
        }
        __syncthreads();

        // ---- diff[r][cc][d] ----
        if (h < R * 9) {
            int r = h / 9, rem = h % 9, cc = rem / 3, d = rem % 3;
            int n = min(base + r, N - 1);
            int b = sbid[r] < 0 ? 0 : sbid[r];
            sdiff[r][cc][d] = vcoord[(b * 3 + d) * C + cc] - coord[n * 3 + d];
        }
        __syncthreads();

        // ---- radial ----
        if (h < R * C) {
            int r = h / C, cc = h % C;
            float x = sdiff[r][cc][0], y = sdiff[r][cc][1], z = sdiff[r][cc][2];
            srad[r][cc] = sqrtf(x * x + y * y + z * z);
        }

        // ---- load node_feat tile ----
#pragma unroll
        for (int r = 0; r < R; r++) {
            int n = min(base + r, N - 1);
            snf[r][h] = node_feat[(long)n * NF + h];
        }
        __syncthreads();

        // ---- layer0: x1[r] = node_feat[r] @ We1[0:128] ----
        float x1[R];
#pragma unroll
        for (int r = 0; r < R; r++) x1[r] = 0.f;
#pragma unroll 2
        for (int k = 0; k < NF; k += 2) {
            float w0 = __ldg(&We1[k * H + h]);
            float w1 = __ldg(&We1[(k + 1) * H + h]);
#pragma unroll
            for (int r = 0; r < R; r++) {
                float2 v = *(const float2*)&snf[r][k];
                x1[r] = fmaf(v.x, w0, x1[r]);
                x1[r] = fmaf(v.y, w1, x1[r]);
            }
        }

        // ---- m1 = silu(x1 + V1[b,c] + radial*wr) -> smem ----
#pragma unroll
        for (int r = 0; r < R; r++) {
            int b = sbid[r] < 0 ? 0 : sbid[r];
#pragma unroll
            for (int cc = 0; cc < C; cc++) {
                float pre = x1[r] + __ldg(&g_V1[(b * C + cc) * H + h])
                          + srad[r][cc] * wr;
                sm[r * C + cc][h] = silu(pre);
            }
        }
        __syncthreads();

        // ---- layer2: m2 = silu(m1 @ We2 + be2) ----
        float m2[ROWS];
#pragma unroll
        for (int q = 0; q < ROWS; q++) m2[q] = be2h;
#pragma unroll 2
        for (int k = 0; k < H; k += 2) {
            float w0 = __ldg(&We2[k * H + h]);
            float w1 = __ldg(&We2[(k + 1) * H + h]);
#pragma unroll
            for (int q = 0; q < ROWS; q++) {
                float2 v = *(const float2*)&sm[q][k];
                m2[q] = fmaf(v.x, w0, m2[q]);
                m2[q] = fmaf(v.y, w1, m2[q]);
            }
        }
#pragma unroll
        for (int q = 0; q < ROWS; q++) m2[q] = silu(m2[q]);
        __syncthreads();                 // all m1 reads done
#pragma unroll
        for (int q = 0; q < ROWS; q++) sm[q][h] = m2[q];
        __syncthreads();

        // ---- coord head: p = silu(m2 @ Wc1 + bc1); s = p . Wc2 ----
        float pq[ROWS];
#pragma unroll
        for (int q = 0; q < ROWS; q++) pq[q] = bc1h;
#pragma unroll 2
        for (int k = 0; k < H; k += 2) {
            float w0 = __ldg(&Wc1[k * H + h]);
            float w1 = __ldg(&Wc1[(k + 1) * H + h]);
#pragma unroll
            for (int q = 0; q < ROWS; q++) {
                float2 v = *(const float2*)&sm[q][k];
                pq[q] = fmaf(v.x, w0, pq[q]);
                pq[q] = fmaf(v.y, w1, pq[q]);
            }
        }
        {
            int lane = h & 31, wid = h >> 5;
#pragma unroll
            for (int q = 0; q < ROWS; q++) {
                float x = silu(pq[q]) * wc2h;
                x += __shfl_xor_sync(0xffffffff, x, 16);
                x += __shfl_xor_sync(0xffffffff, x, 8);
                x += __shfl_xor_sync(0xffffffff, x, 4);
                x += __shfl_xor_sync(0xffffffff, x, 2);
                x += __shfl_xor_sync(0xffffffff, x, 1);
                if (lane == 0) sred[q][wid] = x;
            }
        }
        __syncthreads();
        if (h < ROWS) ss[h] = sred[h][0] + sred[h][1] + sred[h][2] + sred[h][3];
        __syncthreads();

        // ---- segment accumulation (sorted batch -> rare flushes) ----
#pragma unroll
        for (int r = 0; r < R; r++) {
            int b = sbid[r];
            if (b < 0) continue;
            if (b != cur_b) {
                if (cur_b >= 0) {
#pragma unroll
                    for (int cc = 0; cc < C; cc++) {
                        atomicAdd(&g_aggM[(cur_b * C + cc) * H + h], aggM[cc]);
                        aggM[cc] = 0.f;
                    }
                    if (h < 9) {
                        int cc = h / 3, d = h % 3;
                        atomicAdd(&g_aggT[cur_b * 9 + d * 3 + cc], aggT);
                        aggT = 0.f;
                    }
                    if (h == 0) { atomicAdd(&g_cnt[cur_b], cntL); cntL = 0.f; }
                }
                cur_b = b;
            }
#pragma unroll
            for (int cc = 0; cc < C; cc++) aggM[cc] += m2[r * C + cc];
            if (h < 9) {
                int cc = h / 3, d = h % 3;
                aggT += sdiff[r][cc][d] * ss[r * C + cc];
            }
            if (h == 0) cntL += 1.f;
        }
        __syncthreads();   // protect sdiff/ss/sbid before next iteration
    }

    // ---- final flush ----
    if (cur_b >= 0) {
#pragma unroll
        for (int cc = 0; cc < C; cc++)
            atomicAdd(&g_aggM[(cur_b * C + cc) * H + h], aggM[cc]);
        if (h < 9) {
            int cc = h / 3, d = h % 3;
            atomicAdd(&g_aggT[cur_b * 9 + d * 3 + cc], aggT);
        }
        if (h == 0) atomicAdd(&g_cnt[cur_b], cntL);
    }
}

// ---------------------------------------------------------------------------
// finalize: node MLP on B*C rows + write both outputs
// ---------------------------------------------------------------------------
__global__ void final_kernel(const float* __restrict__ vnf,
                             const float* __restrict__ vcoord,
                             const float* __restrict__ Wn1, const float* __restrict__ bn1,
                             const float* __restrict__ Wn2, const float* __restrict__ bn2,
                             float* __restrict__ out, int B) {
    __shared__ float s_in[2 * H];
    __shared__ float s_h1[H];
    int t = threadIdx.x;
    int b = blockIdx.x / C, c = blockIdx.x % C;

    float cnt = fmaxf(g_cnt[b], 1.0f);
    s_in[t]     = vnf[(b * NF + t) * C + c];
    s_in[H + t] = g_aggM[(b * C + c) * H + t] / cnt;
    __syncthreads();

    float acc = bn1[t];
#pragma unroll 4
    for (int k = 0; k < 2 * H; k++)
        acc = fmaf(s_in[k], __ldg(&Wn1[k * H + t]), acc);
    s_h1[t] = silu(acc);
    __syncthreads();

    float acc2 = bn2[t];
#pragma unroll 4
    for (int k = 0; k < H; k++)
        acc2 = fmaf(s_h1[k], __ldg(&Wn2[k * H + t]), acc2);

    // output tensor 1: virtual_node_feat + h^T   [B, NF, C]
    out[(b * NF + t) * C + c] = vnf[(b * NF + t) * C + c] + acc2;

    // output tensor 2: virtual_coord + mean(trans)   [B, 3, C]
    if (c == 0 && t < 9) {
        int d = t / 3, cc = t % 3;
        int idx = (b * 3 + d) * C + cc;
        out[B * NF * C + idx] = vcoord[idx] + g_aggT[idx] / cnt;
    }
}

// ---------------------------------------------------------------------------
extern "C" void kernel_launch(void* const* d_in, const int* in_sizes, int n_in,
                              void* d_out, int out_size) {
    const float* node_feat = (const float*)d_in[0];
    const float* coord     = (const float*)d_in[1];
    const float* vnf       = (const float*)d_in[2];
    const float* vcoord    = (const float*)d_in[3];
    const int*   batch     = (const int*)  d_in[4];
    const float* We1 = (const float*)d_in[5];
    const float* be1 = (const float*)d_in[6];
    const float* We2 = (const float*)d_in[7];
    const float* be2 = (const float*)d_in[8];
    const float* Wc1 = (const float*)d_in[9];
    const float* bc1 = (const float*)d_in[10];
    const float* Wc2 = (const float*)d_in[11];
    const float* Wn1 = (const float*)d_in[12];
    const float* bn1 = (const float*)d_in[13];
    const float* Wn2 = (const float*)d_in[14];
    const float* bn2 = (const float*)d_in[15];

    int N = in_sizes[0] / NF;
    int B = in_sizes[2] / (NF * C);

    prep_kernel<<<B * C, 128>>>(vnf, We1, be1);

    int blocks = (N + NODES_PER_BLOCK - 1) / NODES_PER_BLOCK;
    main_kernel<<<blocks, 128>>>(node_feat, coord, vcoord, batch,
                                 We1, We2, be2, Wc1, bc1, Wc2, N);

    final_kernel<<<B * C, 128>>>(vnf, vcoord, Wn1, bn1, Wn2, bn2,
                                 (float*)d_out, B);
}

// round 4
// speedup vs baseline: 4.4655x; 4.2542x over previous
#include <cuda_runtime.h>
#include <cuda_bf16.h>
#include <cstdint>

// EGCL_A2V — bf16 HMMA (mma.sync.m16n8k16) implementation.
// tcgen05 is unusable (harness PTX target is compute_103 without the 'a'
// feature suffix), so tensor work goes through classic warp-level MMA with
// register accumulators. 7 GEMMs of 128x128x128 per 128-node tile; epilogues
// (silu via tanh.approx) run directly on accumulator registers.

#define NF 128
#define H  128
#define C  3
#define B_MAX 256
#define THREADS 256
#define PAD 136                 // bf16 row stride (272B -> conflict-free frags)
#define WSTRIDE (128*PAD)       // halves per weight image

#define SMEM_SW    0
#define SMEM_SA    104448
#define SMEM_SWR   139264
#define SMEM_TOTAL 148480

__device__ float g_V1[B_MAX * C * H];
__device__ float g_aggM[B_MAX * C * H];
__device__ float g_aggT[B_MAX * 9];
__device__ float g_cnt[B_MAX];
__device__ __align__(16) __nv_bfloat16 g_Wimg[3 * WSTRIDE];  // We1a^T, We2^T, Wc1^T as [n][k]

// ---------------- helpers ----------------
__device__ __forceinline__ float silu_f(float x) {           // 1 MUFU + FMAs
    float t;
    asm("tanh.approx.f32 %0, %1;" : "=f"(t) : "f"(0.5f * x));
    return 0.5f * x * (1.0f + t);
}
__device__ __forceinline__ float silu_p(float x) { return x / (1.0f + __expf(-x)); }

__device__ __forceinline__ uint32_t pack_bf16(float lo, float hi) {
    uint32_t r;
    asm("cvt.rn.bf16x2.f32 %0, %1, %2;" : "=r"(r) : "f"(hi), "f"(lo));
    return r;
}

__device__ __forceinline__ void mma16816(float* d,
        uint32_t a0, uint32_t a1, uint32_t a2, uint32_t a3,
        uint32_t b0, uint32_t b1) {
    asm volatile(
        "mma.sync.aligned.m16n8k16.row.col.f32.bf16.bf16.f32 "
        "{%0,%1,%2,%3}, {%4,%5,%6,%7}, {%8,%9}, {%0,%1,%2,%3};"
        : "+f"(d[0]), "+f"(d[1]), "+f"(d[2]), "+f"(d[3])
        : "r"(a0), "r"(a1), "r"(a2), "r"(a3), "r"(b0), "r"(b1));
}

// D[128,128] += A[128,128] @ W[128,128]; A in sA ([m][k], PAD stride),
// W^T in sW ([n][k], PAD stride). Warp `warp` owns rows [16*warp, 16*warp+16).
__device__ __forceinline__ void gemm128(const __nv_bfloat16* sA,
                                        const __nv_bfloat16* sW,
                                        float* acc, int lane, int warp) {
    const __nv_bfloat16* pa = sA + (warp * 16 + (lane >> 2)) * PAD + (lane & 3) * 2;
    const __nv_bfloat16* pb = sW + (lane >> 2) * PAD + (lane & 3) * 2;
#pragma unroll 1
    for (int ks = 0; ks < 8; ks++) {
        uint32_t a0 = *(const uint32_t*)(pa + ks * 16);
        uint32_t a1 = *(const uint32_t*)(pa + 8 * PAD + ks * 16);
        uint32_t a2 = *(const uint32_t*)(pa + ks * 16 + 8);
        uint32_t a3 = *(const uint32_t*)(pa + 8 * PAD + ks * 16 + 8);
#pragma unroll
        for (int nt = 0; nt < 16; nt++) {
            uint32_t b0 = *(const uint32_t*)(pb + nt * 8 * PAD + ks * 16);
            uint32_t b1 = *(const uint32_t*)(pb + nt * 8 * PAD + ks * 16 + 8);
            mma16816(acc + nt * 4, a0, a1, a2, a3, b0, b1);
        }
    }
}

// ---------------------------------------------------------------------------
// prep_img: bake Wt[n][k] = W[k][n] (bf16, PAD-strided) for the 3 GEMM weights
// ---------------------------------------------------------------------------
__global__ void prep_img(const float* __restrict__ We1,
                         const float* __restrict__ We2,
                         const float* __restrict__ Wc1) {
    int w = blockIdx.x >> 7, k = blockIdx.x & 127, n = threadIdx.x;
    const float* W = (w == 0) ? We1 : (w == 1) ? We2 : Wc1;
    g_Wimg[w * WSTRIDE + n * PAD + k] = __float2bfloat16(W[k * H + n]);
}

// ---------------------------------------------------------------------------
// prep_V1: V1[b,c,h] = be1[h] + sum_f vnf[b,f,c]*We1[128+f,h]; zero accumulators
// ---------------------------------------------------------------------------
__global__ void prep_V1(const float* __restrict__ vnf,
                        const float* __restrict__ We1,
                        const float* __restrict__ be1) {
    int h = threadIdx.x, bc = blockIdx.x;
    int b = bc / C, c = bc % C;
    float acc = be1[h];
    const float* w = We1 + NF * H;
#pragma unroll 4
    for (int f = 0; f < NF; f++)
        acc = fmaf(vnf[(b * NF + f) * C + c], __ldg(&w[f * H + h]), acc);
    g_V1[bc * H + h] = acc;
    g_aggM[bc * H + h] = 0.0f;
    if (bc == 0) {
        for (int i = h; i < B_MAX * 9; i += blockDim.x) g_aggT[i] = 0.0f;
        for (int i = h; i < B_MAX; i += blockDim.x) g_cnt[i] = 0.0f;
    }
}

// ---------------------------------------------------------------------------
// main: persistent CTAs, 128-node tiles, HMMA GEMMs + fused epilogues
// ---------------------------------------------------------------------------
__global__ void __launch_bounds__(THREADS, 1)
main_kernel(const float* __restrict__ node_feat,
            const float* __restrict__ coord,
            const float* __restrict__ vcoord,
            const int*   __restrict__ batch,
            const float* __restrict__ We1,
            const float* __restrict__ be2,
            const float* __restrict__ bc1,
            const float* __restrict__ Wc2,
            int N) {
    extern __shared__ __align__(16) char smem[];
    __nv_bfloat16* sW = (__nv_bfloat16*)(smem + SMEM_SW);
    __nv_bfloat16* sA = (__nv_bfloat16*)(smem + SMEM_SA);
    float* swr  = (float*)(smem + SMEM_SWR);
    float* sbe2 = swr + 128;
    float* sbc1 = sbe2 + 128;
    float* swc2 = sbc1 + 128;
    int*   sbid = (int*)(swc2 + 128);
    float* srad = (float*)(sbid + 128);     // [128][3]
    float* sdiff = srad + 128 * 3;          // [128][9]
    float* ssm  = sdiff + 128 * 9;          // [128]

    const int tid = threadIdx.x, lane = tid & 31, warp = tid >> 5;

    // weights -> smem
    {
        const uint4* src = (const uint4*)g_Wimg;
        uint4* dst = (uint4*)sW;
        for (int i = tid; i < 3 * WSTRIDE * 2 / 16; i += THREADS) dst[i] = src[i];
    }
    if (tid < 128) {
        swr[tid]  = We1[256 * H + tid];
        sbe2[tid] = be2[tid];
        sbc1[tid] = bc1[tid];
        swc2[tid] = Wc2[tid];
    }
    __syncthreads();

    const int ntiles = (N + 127) >> 7;
    for (int t = blockIdx.x; t < ntiles; t += gridDim.x) {
        const int base = t << 7;

        // per-node metadata + geometry (threads 0..127)
        if (tid < 128) {
            int m = tid, n = base + m;
            bool valid = n < N;
            int nc = valid ? n : N - 1;
            int b = valid ? batch[n] : -1;
            sbid[m] = b;
            int bb = b < 0 ? 0 : b;
            float cx = coord[nc * 3 + 0], cy = coord[nc * 3 + 1], cz = coord[nc * 3 + 2];
#pragma unroll
            for (int cc = 0; cc < C; cc++) {
                float dx = __ldg(&vcoord[(bb * 3 + 0) * C + cc]) - cx;
                float dy = __ldg(&vcoord[(bb * 3 + 1) * C + cc]) - cy;
                float dz = __ldg(&vcoord[(bb * 3 + 2) * C + cc]) - cz;
                sdiff[m * 9 + cc * 3 + 0] = dx;
                sdiff[m * 9 + cc * 3 + 1] = dy;
                sdiff[m * 9 + cc * 3 + 2] = dz;
                srad[m * 3 + cc] = sqrtf(dx * dx + dy * dy + dz * dz);
            }
        }
        // node_feat tile -> bf16 sA (all threads; thread = half-row)
        {
            int r = tid >> 1, cb = (tid & 1) * 64;
            int n = base + r;
            int nc = n < N ? n : N - 1;
            const float4* nf = (const float4*)(node_feat + (size_t)nc * NF + cb);
            __nv_bfloat16* dst = sA + r * PAD + cb;
#pragma unroll
            for (int q = 0; q < 16; q++) {
                float4 v = __ldg(&nf[q]);
                *(uint32_t*)(dst + q * 4)     = pack_bf16(v.x, v.y);
                *(uint32_t*)(dst + q * 4 + 2) = pack_bf16(v.z, v.w);
            }
        }
        __syncthreads();

        // node counts (thread 0; overlaps GEMM1 of other warps)
        if (tid == 0) {
            int cb = sbid[0]; float cl = 0.f;
            for (int r = 0; r < 128; r++) {
                int b2 = sbid[r];
                if (b2 != cb) { if (cb >= 0) atomicAdd(&g_cnt[cb], cl); cl = 0.f; cb = b2; }
                if (b2 >= 0) cl += 1.f;
            }
            if (cb >= 0) atomicAdd(&g_cnt[cb], cl);
        }

        // GEMM1: X1 = nf @ We1a^T
        float x1[64];
#pragma unroll
        for (int i = 0; i < 64; i++) x1[i] = 0.f;
        gemm128(sA, sW, x1, lane, warp);
        __syncthreads();   // all warps done reading sA(nf)

        const int r0 = warp * 16 + (lane >> 2), r1 = r0 + 8;
        int bb0 = sbid[r0]; bb0 = bb0 < 0 ? 0 : bb0;
        int bb1 = sbid[r1]; bb1 = bb1 < 0 ? 0 : bb1;

#pragma unroll 1
        for (int c = 0; c < C; c++) {
            // Epilogue A: m1 = silu(X1 + V1[b,c] + rad*wr) -> sA (bf16)
            float rad0 = srad[r0 * 3 + c], rad1 = srad[r1 * 3 + c];
            const float* V1p0 = g_V1 + (bb0 * C + c) * H;
            const float* V1p1 = g_V1 + (bb1 * C + c) * H;
#pragma unroll
            for (int nt = 0; nt < 16; nt++) {
                int c0 = nt * 8 + (lane & 3) * 2;
                float f00 = x1[nt * 4 + 0] + __ldg(&V1p0[c0])     + rad0 * swr[c0];
                float f01 = x1[nt * 4 + 1] + __ldg(&V1p0[c0 + 1]) + rad0 * swr[c0 + 1];
                float f10 = x1[nt * 4 + 2] + __ldg(&V1p1[c0])     + rad1 * swr[c0];
                float f11 = x1[nt * 4 + 3] + __ldg(&V1p1[c0 + 1]) + rad1 * swr[c0 + 1];
                *(uint32_t*)(sA + r0 * PAD + c0) = pack_bf16(silu_f(f00), silu_f(f01));
                *(uint32_t*)(sA + r1 * PAD + c0) = pack_bf16(silu_f(f10), silu_f(f11));
            }
            __syncthreads();

            // GEMM2: M2pre = m1 @ We2^T
            float acc[64];
#pragma unroll
            for (int i = 0; i < 64; i++) acc[i] = 0.f;
            gemm128(sA, sW + WSTRIDE, acc, lane, warp);
            __syncthreads();   // all warps done reading sA(m1)

            // Epilogue B: m2 = silu(M2pre + be2) -> sA (bf16)
#pragma unroll
            for (int nt = 0; nt < 16; nt++) {
                int c0 = nt * 8 + (lane & 3) * 2;
                float m00 = silu_f(acc[nt * 4 + 0] + sbe2[c0]);
                float m01 = silu_f(acc[nt * 4 + 1] + sbe2[c0 + 1]);
                float m10 = silu_f(acc[nt * 4 + 2] + sbe2[c0]);
                float m11 = silu_f(acc[nt * 4 + 3] + sbe2[c0 + 1]);
                *(uint32_t*)(sA + r0 * PAD + c0) = pack_bf16(m00, m01);
                *(uint32_t*)(sA + r1 * PAD + c0) = pack_bf16(m10, m11);
            }
            __syncthreads();

            // GEMM3: Ppre = m2 @ Wc1^T
#pragma unroll
            for (int i = 0; i < 64; i++) acc[i] = 0.f;
            gemm128(sA, sW + 2 * WSTRIDE, acc, lane, warp);

            // Epilogue C: s = sum_h silu(Ppre + bc1)*Wc2 (row sums via shfl)
            {
                float s0 = 0.f, s1 = 0.f;
#pragma unroll
                for (int nt = 0; nt < 16; nt++) {
                    int c0 = nt * 8 + (lane & 3) * 2;
                    s0 += silu_f(acc[nt * 4 + 0] + sbc1[c0]) * swc2[c0]
                        + silu_f(acc[nt * 4 + 1] + sbc1[c0 + 1]) * swc2[c0 + 1];
                    s1 += silu_f(acc[nt * 4 + 2] + sbc1[c0]) * swc2[c0]
                        + silu_f(acc[nt * 4 + 3] + sbc1[c0 + 1]) * swc2[c0 + 1];
                }
                s0 += __shfl_xor_sync(0xffffffffu, s0, 1);
                s0 += __shfl_xor_sync(0xffffffffu, s0, 2);
                s1 += __shfl_xor_sync(0xffffffffu, s1, 1);
                s1 += __shfl_xor_sync(0xffffffffu, s1, 2);
                if ((lane & 3) == 0) { ssm[r0] = s0; ssm[r1] = s1; }
            }

            // aggM: per-column segment sums of m2 (from bf16 sA)
            if (tid < 128) {
                int col = tid; float a = 0.f; int cb = sbid[0];
                for (int r = 0; r < 128; r++) {
                    int b2 = sbid[r];
                    if (b2 != cb) {
                        if (cb >= 0) atomicAdd(&g_aggM[(cb * C + c) * H + col], a);
                        a = 0.f; cb = b2;
                    }
                    if (b2 >= 0) a += __bfloat162float(sA[r * PAD + col]);
                }
                if (cb >= 0) atomicAdd(&g_aggM[(cb * C + c) * H + col], a);
            }
            __syncthreads();   // ssm visible; sA readers done

            // aggT: segment sums of diff * s
            if (tid < 3) {
                int d = tid; float a = 0.f; int cb = sbid[0];
                for (int r = 0; r < 128; r++) {
                    int b2 = sbid[r];
                    if (b2 != cb) {
                        if (cb >= 0) atomicAdd(&g_aggT[cb * 9 + d * 3 + c], a);
                        a = 0.f; cb = b2;
                    }
                    if (b2 >= 0) a += sdiff[r * 9 + c * 3 + d] * ssm[r];
                }
                if (cb >= 0) atomicAdd(&g_aggT[cb * 9 + d * 3 + c], a);
            }
            __syncthreads();   // aggT done before ssm/sA reuse
        }
    }
}

// ---------------------------------------------------------------------------
// finalize: node MLP on B*C rows + write both outputs (fp32)
// ---------------------------------------------------------------------------
__global__ void final_kernel(const float* __restrict__ vnf,
                             const float* __restrict__ vcoord,
                             const float* __restrict__ Wn1, const float* __restrict__ bn1,
                             const float* __restrict__ Wn2, const float* __restrict__ bn2,
                             float* __restrict__ out, int B) {
    __shared__ float s_in[2 * H];
    __shared__ float s_h1[H];
    int t = threadIdx.x;
    int b = blockIdx.x / C, c = blockIdx.x % C;

    float cnt = fmaxf(g_cnt[b], 1.0f);
    s_in[t]     = vnf[(b * NF + t) * C + c];
    s_in[H + t] = g_aggM[(b * C + c) * H + t] / cnt;
    __syncthreads();

    float acc = bn1[t];
#pragma unroll 4
    for (int k = 0; k < 2 * H; k++)
        acc = fmaf(s_in[k], __ldg(&Wn1[k * H + t]), acc);
    s_h1[t] = silu_p(acc);
    __syncthreads();

    float acc2 = bn2[t];
#pragma unroll 4
    for (int k = 0; k < H; k++)
        acc2 = fmaf(s_h1[k], __ldg(&Wn2[k * H + t]), acc2);

    out[(b * NF + t) * C + c] = vnf[(b * NF + t) * C + c] + acc2;

    if (c == 0 && t < 9) {
        int d = t / 3, cc = t % 3;
        int idx = (b * 3 + d) * C + cc;
        out[B * NF * C + idx] = vcoord[idx] + g_aggT[idx] / cnt;
    }
}

// ---------------------------------------------------------------------------
extern "C" void kernel_launch(void* const* d_in, const int* in_sizes, int n_in,
                              void* d_out, int out_size) {
    const float* node_feat = (const float*)d_in[0];
    const float* coord     = (const float*)d_in[1];
    const float* vnf       = (const float*)d_in[2];
    const float* vcoord    = (const float*)d_in[3];
    const int*   batch     = (const int*)  d_in[4];
    const float* We1 = (const float*)d_in[5];
    const float* be1 = (const float*)d_in[6];
    const float* We2 = (const float*)d_in[7];
    const float* be2 = (const float*)d_in[8];
    const float* Wc1 = (const float*)d_in[9];
    const float* bc1 = (const float*)d_in[10];
    const float* Wc2 = (const float*)d_in[11];
    const float* Wn1 = (const float*)d_in[12];
    const float* bn1 = (const float*)d_in[13];
    const float* Wn2 = (const float*)d_in[14];
    const float* bn2 = (const float*)d_in[15];

    int N = in_sizes[0] / NF;
    int B = in_sizes[2] / (NF * C);

    cudaFuncSetAttribute(main_kernel,
                         cudaFuncAttributeMaxDynamicSharedMemorySize, SMEM_TOTAL);

    prep_img<<<3 * 128, 128>>>(We1, We2, Wc1);
    prep_V1<<<B * C, 128>>>(vnf, We1, be1);
    main_kernel<<<148, THREADS, SMEM_TOTAL>>>(node_feat, coord, vcoord, batch,
                                              We1, be2, bc1, Wc2, N);
    final_kernel<<<B * C, 128>>>(vnf, vcoord, Wn1, bn1, Wn2, bn2,
                                 (float*)d_out, B);
}

// round 5
// speedup vs baseline: 6.2800x; 1.4063x over previous
#include <cuda_runtime.h>
#include <cuda_bf16.h>
#include <cstdint>

// EGCL_A2V — bf16 HMMA + ldmatrix + fast-path parallel segment reductions.
// 7 GEMMs of 128x128x128 per 128-node tile on the tensor pipe; epilogues
// (silu via tanh.approx) act on register accumulators. Sorted data_batch =>
// most tiles are single-segment => register/warp-shuffle reductions instead
// of serial 128-row scans.

#define NF 128
#define H  128
#define C  3
#define B_MAX 256
#define THREADS 256
#define PAD 136                 // bf16 row stride (272B = 17*16B: ldmatrix conflict-free)
#define WSTRIDE (128*PAD)       // elements per weight image

#define SMEM_SW    0
#define SMEM_SA    104448
#define SMEM_F     139264
#define SMEM_TOTAL 154112

__device__ float g_V1[B_MAX * C * H];
__device__ float g_aggM[B_MAX * C * H];
__device__ float g_aggT[B_MAX * 9];
__device__ float g_cnt[B_MAX];
__device__ __align__(16) __nv_bfloat16 g_Wimg[3 * WSTRIDE];  // We1a^T, We2^T, Wc1^T as [n][k]

// ---------------- helpers ----------------
__device__ __forceinline__ float silu_f(float x) {
    float t;
    asm("tanh.approx.f32 %0, %1;" : "=f"(t) : "f"(0.5f * x));
    return 0.5f * x * (1.0f + t);
}
__device__ __forceinline__ float silu_p(float x) { return x / (1.0f + __expf(-x)); }

__device__ __forceinline__ uint32_t pack_bf16(float lo, float hi) {
    uint32_t r;
    asm("cvt.rn.bf16x2.f32 %0, %1, %2;" : "=r"(r) : "f"(hi), "f"(lo));
    return r;
}
__device__ __forceinline__ uint32_t smem_u32(const void* p) {
    uint32_t a;
    asm("{ .reg .u64 t; cvta.to.shared.u64 t, %1; cvt.u32.u64 %0, t; }" : "=r"(a) : "l"(p));
    return a;
}
__device__ __forceinline__ void ldsm_x4(uint32_t* r, uint32_t addr) {
    asm volatile("ldmatrix.sync.aligned.m8n8.x4.shared.b16 {%0,%1,%2,%3}, [%4];"
                 : "=r"(r[0]), "=r"(r[1]), "=r"(r[2]), "=r"(r[3]) : "r"(addr));
}
__device__ __forceinline__ void mma16816(float* d,
        uint32_t a0, uint32_t a1, uint32_t a2, uint32_t a3,
        uint32_t b0, uint32_t b1) {
    asm volatile(
        "mma.sync.aligned.m16n8k16.row.col.f32.bf16.bf16.f32 "
        "{%0,%1,%2,%3}, {%4,%5,%6,%7}, {%8,%9}, {%0,%1,%2,%3};"
        : "+f"(d[0]), "+f"(d[1]), "+f"(d[2]), "+f"(d[3])
        : "r"(a0), "r"(a1), "r"(a2), "r"(a3), "r"(b0), "r"(b1));
}

// D[128,128] += A[128,128] @ W^T; A at aAddr (per-thread ldmatrix base),
// W image at bAddr (per-thread ldmatrix base). acc[nt*4+j] layout:
// row r0=warp*16+(lane>>2) (+8 for j>=2), col nt*8+(lane&3)*2 (+1 for odd j).
__device__ __forceinline__ void gemm128(uint32_t aAddr, uint32_t bAddr, float* acc) {
#pragma unroll 2
    for (int ks = 0; ks < 8; ks++) {
        uint32_t A[4];
        ldsm_x4(A, aAddr + ks * 32);
#pragma unroll
        for (int ntp = 0; ntp < 8; ntp++) {
            uint32_t Bf[4];
            ldsm_x4(Bf, bAddr + ntp * (16 * PAD * 2) + ks * 32);
            mma16816(acc + ntp * 8,     A[0], A[1], A[2], A[3], Bf[0], Bf[1]);
            mma16816(acc + ntp * 8 + 4, A[0], A[1], A[2], A[3], Bf[2], Bf[3]);
        }
    }
}

// ---------------------------------------------------------------------------
__global__ void prep_img(const float* __restrict__ We1,
                         const float* __restrict__ We2,
                         const float* __restrict__ Wc1) {
    int w = blockIdx.x >> 7, k = blockIdx.x & 127, n = threadIdx.x;
    const float* W = (w == 0) ? We1 : (w == 1) ? We2 : Wc1;
    g_Wimg[w * WSTRIDE + n * PAD + k] = __float2bfloat16(W[k * H + n]);
}

// ---------------------------------------------------------------------------
__global__ void prep_V1(const float* __restrict__ vnf,
                        const float* __restrict__ We1,
                        const float* __restrict__ be1) {
    __shared__ float sv[NF];
    int h = threadIdx.x, bc = blockIdx.x;
    int b = bc / C, c = bc % C;
    sv[h] = vnf[(b * NF + h) * C + c];
    __syncthreads();
    const float* w = We1 + NF * H;
    float a0 = 0.f, a1 = 0.f, a2 = 0.f, a3 = 0.f;
#pragma unroll 8
    for (int f = 0; f < NF; f += 4) {
        a0 = fmaf(sv[f],     __ldg(&w[(f)     * H + h]), a0);
        a1 = fmaf(sv[f + 1], __ldg(&w[(f + 1) * H + h]), a1);
        a2 = fmaf(sv[f + 2], __ldg(&w[(f + 2) * H + h]), a2);
        a3 = fmaf(sv[f + 3], __ldg(&w[(f + 3) * H + h]), a3);
    }
    g_V1[bc * H + h] = be1[h] + ((a0 + a1) + (a2 + a3));
    g_aggM[bc * H + h] = 0.0f;
    if (bc == 0) {
        for (int i = h; i < B_MAX * 9; i += blockDim.x) g_aggT[i] = 0.0f;
        for (int i = h; i < B_MAX; i += blockDim.x) g_cnt[i] = 0.0f;
    }
}

// ---------------------------------------------------------------------------
__global__ void __launch_bounds__(THREADS, 1)
main_kernel(const float* __restrict__ node_feat,
            const float* __restrict__ coord,
            const float* __restrict__ vcoord,
            const int*   __restrict__ batch,
            const float* __restrict__ We1,
            const float* __restrict__ be2,
            const float* __restrict__ bc1,
            const float* __restrict__ Wc2,
            int N) {
    extern __shared__ __align__(16) char smem[];
    __nv_bfloat16* sW = (__nv_bfloat16*)(smem + SMEM_SW);
    __nv_bfloat16* sA = (__nv_bfloat16*)(smem + SMEM_SA);
    float* swr   = (float*)(smem + SMEM_F);
    float* sbe2  = swr + 128;
    float* sbc1  = sbe2 + 128;
    float* swc2  = sbc1 + 128;
    int*   sbid  = (int*)(swc2 + 128);
    float* srad  = (float*)(sbid + 128);    // [128][3]
    float* sdiff = srad + 128 * 3;          // [128][9]
    float* ssm   = sdiff + 128 * 9;         // [128]
    float* swp   = ssm + 128;               // [8][128] warp col-sum partials
    float* st    = swp + 8 * 128;           // [3][128] aggT products
    __shared__ int s_fast;

    const int tid = threadIdx.x, lane = tid & 31, warp = tid >> 5;

    // weights -> smem
    {
        const uint4* src = (const uint4*)g_Wimg;
        uint4* dst = (uint4*)sW;
        for (int i = tid; i < 3 * WSTRIDE * 2 / 16; i += THREADS) dst[i] = src[i];
    }
    if (tid < 128) {
        swr[tid]  = We1[256 * H + tid];
        sbe2[tid] = be2[tid];
        sbc1[tid] = bc1[tid];
        swc2[tid] = Wc2[tid];
    }
    __syncthreads();

    // ldmatrix base addresses
    const uint32_t sA_u = smem_u32(sA);
    const uint32_t sW_u = smem_u32(sW);
    const uint32_t aAddr = sA_u +
        (((warp * 16 + (lane & 15)) * PAD + (lane >> 4) * 8) << 1);
    const uint32_t bRel =
        (((((lane >> 4) & 1) * 8 + (lane & 7)) * PAD + ((lane >> 3) & 1) * 8) << 1);
    const uint32_t bAddr0 = sW_u + bRel;
    const uint32_t bAddr1 = bAddr0 + WSTRIDE * 2;
    const uint32_t bAddr2 = bAddr1 + WSTRIDE * 2;

    const int ntiles = (N + 127) >> 7;
    for (int t = blockIdx.x; t < ntiles; t += gridDim.x) {
        const int base = t << 7;

        // per-node metadata + geometry (threads 0..127)
        if (tid < 128) {
            int m = tid, n = base + m;
            bool valid = n < N;
            int nc = valid ? n : N - 1;
            int b = valid ? batch[n] : -1;
            sbid[m] = b;
            int bb = b < 0 ? 0 : b;
            float cx = coord[nc * 3 + 0], cy = coord[nc * 3 + 1], cz = coord[nc * 3 + 2];
#pragma unroll
            for (int cc = 0; cc < C; cc++) {
                float dx = __ldg(&vcoord[(bb * 3 + 0) * C + cc]) - cx;
                float dy = __ldg(&vcoord[(bb * 3 + 1) * C + cc]) - cy;
                float dz = __ldg(&vcoord[(bb * 3 + 2) * C + cc]) - cz;
                sdiff[m * 9 + cc * 3 + 0] = dx;
                sdiff[m * 9 + cc * 3 + 1] = dy;
                sdiff[m * 9 + cc * 3 + 2] = dz;
                srad[m * 3 + cc] = sqrtf(dx * dx + dy * dy + dz * dz);
            }
        }
        // node_feat tile -> bf16 sA
        {
            int r = tid >> 1, cb = (tid & 1) * 64;
            int n = base + r;
            int nc = n < N ? n : N - 1;
            const float4* nf = (const float4*)(node_feat + (size_t)nc * NF + cb);
            __nv_bfloat16* dst = sA + r * PAD + cb;
#pragma unroll
            for (int q = 0; q < 16; q++) {
                float4 v = __ldg(&nf[q]);
                *(uint32_t*)(dst + q * 4)     = pack_bf16(v.x, v.y);
                *(uint32_t*)(dst + q * 4 + 2) = pack_bf16(v.z, v.w);
            }
        }
        if (tid == 0) s_fast = 0;
        __syncthreads();
        if (tid == 0) {
            int b0 = sbid[0];
            if (b0 >= 0 && b0 == sbid[127]) {
                s_fast = 1;
                atomicAdd(&g_cnt[b0], 128.f);
            } else {
                int cb = b0; float cl = 0.f;
                for (int r = 0; r < 128; r++) {
                    int b2 = sbid[r];
                    if (b2 != cb) { if (cb >= 0) atomicAdd(&g_cnt[cb], cl); cl = 0.f; cb = b2; }
                    if (b2 >= 0) cl += 1.f;
                }
                if (cb >= 0) atomicAdd(&g_cnt[cb], cl);
            }
        }

        // GEMM1: X1 = nf @ We1a^T
        float x1[64];
#pragma unroll
        for (int i = 0; i < 64; i++) x1[i] = 0.f;
        gemm128(aAddr, bAddr0, x1);
        __syncthreads();   // sA(nf) consumed; s_fast visible

        const bool fast = (s_fast != 0);
        const int b0t = sbid[0] < 0 ? 0 : sbid[0];
        const int r0 = warp * 16 + (lane >> 2), r1 = r0 + 8;
        int bb0 = sbid[r0]; bb0 = bb0 < 0 ? 0 : bb0;
        int bb1 = sbid[r1]; bb1 = bb1 < 0 ? 0 : bb1;

#pragma unroll 1
        for (int c = 0; c < C; c++) {
            // Epilogue A: m1 = silu(X1 + V1[b,c] + rad*wr) -> sA (bf16)
            float rad0 = srad[r0 * 3 + c], rad1 = srad[r1 * 3 + c];
            const float* V1p0 = g_V1 + (bb0 * C + c) * H;
            const float* V1p1 = g_V1 + (bb1 * C + c) * H;
#pragma unroll
            for (int nt = 0; nt < 16; nt++) {
                int c0 = nt * 8 + (lane & 3) * 2;
                float f00 = x1[nt * 4 + 0] + __ldg(&V1p0[c0])     + rad0 * swr[c0];
                float f01 = x1[nt * 4 + 1] + __ldg(&V1p0[c0 + 1]) + rad0 * swr[c0 + 1];
                float f10 = x1[nt * 4 + 2] + __ldg(&V1p1[c0])     + rad1 * swr[c0];
                float f11 = x1[nt * 4 + 3] + __ldg(&V1p1[c0 + 1]) + rad1 * swr[c0 + 1];
                *(uint32_t*)(sA + r0 * PAD + c0) = pack_bf16(silu_f(f00), silu_f(f01));
                *(uint32_t*)(sA + r1 * PAD + c0) = pack_bf16(silu_f(f10), silu_f(f11));
            }
            __syncthreads();

            // GEMM2: M2pre = m1 @ We2^T
            float acc[64];
#pragma unroll
            for (int i = 0; i < 64; i++) acc[i] = 0.f;
            gemm128(aAddr, bAddr1, acc);
            __syncthreads();   // sA(m1) consumed

            // Epilogue B: m2 = silu(M2pre + be2) -> sA; fast-path col sums -> swp
#pragma unroll
            for (int nt = 0; nt < 16; nt++) {
                int c0 = nt * 8 + (lane & 3) * 2;
                float m00 = silu_f(acc[nt * 4 + 0] + sbe2[c0]);
                float m01 = silu_f(acc[nt * 4 + 1] + sbe2[c0 + 1]);
                float m10 = silu_f(acc[nt * 4 + 2] + sbe2[c0]);
                float m11 = silu_f(acc[nt * 4 + 3] + sbe2[c0 + 1]);
                *(uint32_t*)(sA + r0 * PAD + c0) = pack_bf16(m00, m01);
                *(uint32_t*)(sA + r1 * PAD + c0) = pack_bf16(m10, m11);
                if (fast) {
                    float v0 = m00 + m10, v1 = m01 + m11;
                    v0 += __shfl_xor_sync(0xffffffffu, v0, 4);
                    v0 += __shfl_xor_sync(0xffffffffu, v0, 8);
                    v0 += __shfl_xor_sync(0xffffffffu, v0, 16);
                    v1 += __shfl_xor_sync(0xffffffffu, v1, 4);
                    v1 += __shfl_xor_sync(0xffffffffu, v1, 8);
                    v1 += __shfl_xor_sync(0xffffffffu, v1, 16);
                    if (lane < 4) {
                        swp[warp * 128 + c0]     = v0;
                        swp[warp * 128 + c0 + 1] = v1;
                    }
                }
            }
            __syncthreads();

            // GEMM3: Ppre = m2 @ Wc1^T
#pragma unroll
            for (int i = 0; i < 64; i++) acc[i] = 0.f;
            gemm128(aAddr, bAddr2, acc);

            // Epilogue C: s = sum_h silu(Ppre + bc1)*Wc2
            {
                float s0 = 0.f, s1 = 0.f;
#pragma unroll
                for (int nt = 0; nt < 16; nt++) {
                    int c0 = nt * 8 + (lane & 3) * 2;
                    s0 += silu_f(acc[nt * 4 + 0] + sbc1[c0]) * swc2[c0]
                        + silu_f(acc[nt * 4 + 1] + sbc1[c0 + 1]) * swc2[c0 + 1];
                    s1 += silu_f(acc[nt * 4 + 2] + sbc1[c0]) * swc2[c0]
                        + silu_f(acc[nt * 4 + 3] + sbc1[c0 + 1]) * swc2[c0 + 1];
                }
                s0 += __shfl_xor_sync(0xffffffffu, s0, 1);
                s0 += __shfl_xor_sync(0xffffffffu, s0, 2);
                s1 += __shfl_xor_sync(0xffffffffu, s1, 1);
                s1 += __shfl_xor_sync(0xffffffffu, s1, 2);
                if ((lane & 3) == 0) { ssm[r0] = s0; ssm[r1] = s1; }
            }

            // aggM
            if (fast) {
                if (tid < 128) {
                    float s = 0.f;
#pragma unroll
                    for (int w = 0; w < 8; w++) s += swp[w * 128 + tid];
                    atomicAdd(&g_aggM[(b0t * C + c) * H + tid], s);
                }
            } else if (tid < 128) {
                int col = tid; float a = 0.f; int cb = sbid[0];
                for (int r = 0; r < 128; r++) {
                    int b2 = sbid[r];
                    if (b2 != cb) {
                        if (cb >= 0) atomicAdd(&g_aggM[(cb * C + c) * H + col], a);
                        a = 0.f; cb = b2;
                    }
                    if (b2 >= 0) a += __bfloat162float(sA[r * PAD + col]);
                }
                if (cb >= 0) atomicAdd(&g_aggM[(cb * C + c) * H + col], a);
            }
            __syncthreads();   // ssm visible

            // aggT
            if (fast) {
                if (tid < 128) {
                    float sv = ssm[tid];
#pragma unroll
                    for (int d = 0; d < 3; d++)
                        st[d * 128 + tid] = sdiff[tid * 9 + c * 3 + d] * sv;
                }
                __syncthreads();
                if (warp < 3) {
                    float v = st[warp * 128 + lane] + st[warp * 128 + lane + 32]
                            + st[warp * 128 + lane + 64] + st[warp * 128 + lane + 96];
                    v += __shfl_xor_sync(0xffffffffu, v, 16);
                    v += __shfl_xor_sync(0xffffffffu, v, 8);
                    v += __shfl_xor_sync(0xffffffffu, v, 4);
                    v += __shfl_xor_sync(0xffffffffu, v, 2);
                    v += __shfl_xor_sync(0xffffffffu, v, 1);
                    if (lane == 0)
                        atomicAdd(&g_aggT[b0t * 9 + warp * 3 + c], v);
                }
            } else if (tid < 3) {
                int d = tid; float a = 0.f; int cb = sbid[0];
                for (int r = 0; r < 128; r++) {
                    int b2 = sbid[r];
                    if (b2 != cb) {
                        if (cb >= 0) atomicAdd(&g_aggT[cb * 9 + d * 3 + c], a);
                        a = 0.f; cb = b2;
                    }
                    if (b2 >= 0) a += sdiff[r * 9 + c * 3 + d] * ssm[r];
                }
                if (cb >= 0) atomicAdd(&g_aggT[cb * 9 + d * 3 + c], a);
            }
            __syncthreads();   // reductions done before sA/ssm reuse
        }
    }
}

// ---------------------------------------------------------------------------
// finalize: node MLP on B*C rows + write both outputs (fp32, high-MLP)
// ---------------------------------------------------------------------------
__global__ void final_kernel(const float* __restrict__ vnf,
                             const float* __restrict__ vcoord,
                             const float* __restrict__ Wn1, const float* __restrict__ bn1,
                             const float* __restrict__ Wn2, const float* __restrict__ bn2,
                             float* __restrict__ out, int B) {
    __shared__ float s_in[2 * H];
    __shared__ float s_h1[H];
    int t = threadIdx.x;
    int b = blockIdx.x / C, c = blockIdx.x % C;

    float cnt = fmaxf(g_cnt[b], 1.0f);
    s_in[t]     = vnf[(b * NF + t) * C + c];
    s_in[H + t] = g_aggM[(b * C + c) * H + t] / cnt;
    __syncthreads();

    float a0 = 0.f, a1 = 0.f, a2 = 0.f, a3 = 0.f;
#pragma unroll 16
    for (int k = 0; k < 2 * H; k += 4) {
        a0 = fmaf(s_in[k],     __ldg(&Wn1[(k)     * H + t]), a0);
        a1 = fmaf(s_in[k + 1], __ldg(&Wn1[(k + 1) * H + t]), a1);
        a2 = fmaf(s_in[k + 2], __ldg(&Wn1[(k + 2) * H + t]), a2);
        a3 = fmaf(s_in[k + 3], __ldg(&Wn1[(k + 3) * H + t]), a3);
    }
    s_h1[t] = silu_p(bn1[t] + ((a0 + a1) + (a2 + a3)));
    __syncthreads();

    float b0 = 0.f, b1 = 0.f, b2 = 0.f, b3 = 0.f;
#pragma unroll 16
    for (int k = 0; k < H; k += 4) {
        b0 = fmaf(s_h1[k],     __ldg(&Wn2[(k)     * H + t]), b0);
        b1 = fmaf(s_h1[k + 1], __ldg(&Wn2[(k + 1) * H + t]), b1);
        b2 = fmaf(s_h1[k + 2], __ldg(&Wn2[(k + 2) * H + t]), b2);
        b3 = fmaf(s_h1[k + 3], __ldg(&Wn2[(k + 3) * H + t]), b3);
    }
    float acc2 = bn2[t] + ((b0 + b1) + (b2 + b3));

    out[(b * NF + t) * C + c] = vnf[(b * NF + t) * C + c] + acc2;

    if (c == 0 && t < 9) {
        int d = t / 3, cc = t % 3;
        int idx = (b * 3 + d) * C + cc;
        out[B * NF * C + idx] = vcoord[idx] + g_aggT[idx] / cnt;
    }
}

// ---------------------------------------------------------------------------
extern "C" void kernel_launch(void* const* d_in, const int* in_sizes, int n_in,
                              void* d_out, int out_size) {
    const float* node_feat = (const float*)d_in[0];
    const float* coord     = (const float*)d_in[1];
    const float* vnf       = (const float*)d_in[2];
    const float* vcoord    = (const float*)d_in[3];
    const int*   batch     = (const int*)  d_in[4];
    const float* We1 = (const float*)d_in[5];
    const float* be1 = (const float*)d_in[6];
    const float* We2 = (const float*)d_in[7];
    const float* be2 = (const float*)d_in[8];
    const float* Wc1 = (const float*)d_in[9];
    const float* bc1 = (const float*)d_in[10];
    const float* Wc2 = (const float*)d_in[11];
    const float* Wn1 = (const float*)d_in[12];
    const float* bn1 = (const float*)d_in[13];
    const float* Wn2 = (const float*)d_in[14];
    const float* bn2 = (const float*)d_in[15];

    int N = in_sizes[0] / NF;
    int B = in_sizes[2] / (NF * C);

    cudaFuncSetAttribute(main_kernel,
                         cudaFuncAttributeMaxDynamicSharedMemorySize, SMEM_TOTAL);

    prep_img<<<3 * 128, 128>>>(We1, We2, Wc1);
    prep_V1<<<B * C, 128>>>(vnf, We1, be1);
    main_kernel<<<148, THREADS, SMEM_TOTAL>>>(node_feat, coord, vcoord, batch,
                                              We1, be2, bc1, Wc2, N);
    final_kernel<<<B * C, 128>>>(vnf, vcoord, Wn1, bn1, Wn2, bn2,
                                 (float*)d_out, B);
}